// round 3
// baseline (speedup 1.0000x reference)
#include <cuda_runtime.h>

// ---------------------------------------------------------------------------
// StarLoss: mean over B*N of  w1[i]*D1 + w2[i]*D2 + 0.5*omega*(lam1+lam2)[i]
// where D1 = sum_j p1[j]^2, D2 = sum_j p2[j]^2 are GLOBAL sums.
// => single streaming pass accumulating 5 scalars, then a tiny finalize.
// Traffic: 32 B/element * 2^24 = 537 MB  -> HBM-bound, floor ~80 us.
// ---------------------------------------------------------------------------

#define STAR_EPS 1e-5f

// accumulators: [0]=D1, [1]=D2, [2]=Sum w1, [3]=Sum w2, [4]=Sum trace
__device__ double g_acc[5];

__global__ void star_zero_kernel() {
    if (threadIdx.x < 5) g_acc[threadIdx.x] = 0.0;
}

__device__ __forceinline__ void star_elem(
    float a, float b, float d,
    float px, float py, float tx, float ty,
    float& acc_d1, float& acc_d2, float& acc_w1, float& acc_w2, float& acc_tr)
{
    float mean = 0.5f * (a + d);
    float h    = 0.5f * (a - d);
    float D2   = fmaf(h, h, b * b);
    float rin  = rsqrtf(D2);                 // MUFU.RSQ
    float delta = (D2 > 0.0f) ? D2 * rin : 0.0f;
    float lam1 = mean + delta;
    float lam2 = mean - delta;

    // eigenvector for lam1 (reference formula, incl. diagonal fallback)
    bool diag = fabsf(b) < 1e-12f;
    bool ag   = (a >= d);
    float vx = diag ? (ag ? 1.0f : 0.0f) : b;
    float vy = diag ? (ag ? 0.0f : 1.0f) : (lam1 - a);
    float n2 = fmaf(vx, vx, vy * vy);
    float invn = rsqrtf(n2);                 // MUFU.RSQ
    float invn2 = invn * invn;

    float dx = px - tx;
    float dy = py - ty;
    float t1 = fmaf(vx, dx,  vy * dy);       //  v . r
    float t2 = fmaf(vx, dy, -vy * dx);       //  v_perp . r

    acc_d1 += t1 * t1 * invn2;
    acc_d2 += t2 * t2 * invn2;
    acc_w1 += rsqrtf(lam1) + STAR_EPS;       // MUFU.RSQ  (lam1 >= 0.1)
    acc_w2 += rsqrtf(lam2) + STAR_EPS;       // MUFU.RSQ  (lam2 >= 0.1)
    acc_tr += a + d;                          // lam1 + lam2 == trace
}

__global__ __launch_bounds__(256)
void star_main_kernel(const float4* __restrict__ pred2,   // npairs float4 (2 elems each)
                      const float4* __restrict__ cov,     // 2*npairs float4 (1 elem each)
                      const float4* __restrict__ targ2,   // npairs float4
                      int npairs)
{
    float acc_d1 = 0.f, acc_d2 = 0.f, acc_w1 = 0.f, acc_w2 = 0.f, acc_tr = 0.f;

    int stride = gridDim.x * blockDim.x;
    #pragma unroll 2
    for (int i = blockIdx.x * blockDim.x + threadIdx.x; i < npairs; i += stride) {
        float4 p  = pred2[i];
        float4 t  = targ2[i];
        float4 c0 = cov[2 * i];
        float4 c1 = cov[2 * i + 1];
        // cov element layout: [a, b, b, d] -> use .x, .y, .w
        star_elem(c0.x, c0.y, c0.w, p.x, p.y, t.x, t.y,
                  acc_d1, acc_d2, acc_w1, acc_w2, acc_tr);
        star_elem(c1.x, c1.y, c1.w, p.z, p.w, t.z, t.w,
                  acc_d1, acc_d2, acc_w1, acc_w2, acc_tr);
    }

    // ---- warp reduction (5 values) ----
    #pragma unroll
    for (int off = 16; off > 0; off >>= 1) {
        acc_d1 += __shfl_down_sync(0xFFFFFFFFu, acc_d1, off);
        acc_d2 += __shfl_down_sync(0xFFFFFFFFu, acc_d2, off);
        acc_w1 += __shfl_down_sync(0xFFFFFFFFu, acc_w1, off);
        acc_w2 += __shfl_down_sync(0xFFFFFFFFu, acc_w2, off);
        acc_tr += __shfl_down_sync(0xFFFFFFFFu, acc_tr, off);
    }

    // ---- block reduction across 8 warps ----
    __shared__ float s[5][8];
    int lane = threadIdx.x & 31;
    int wid  = threadIdx.x >> 5;
    if (lane == 0) {
        s[0][wid] = acc_d1; s[1][wid] = acc_d2;
        s[2][wid] = acc_w1; s[3][wid] = acc_w2; s[4][wid] = acc_tr;
    }
    __syncthreads();
    if (wid == 0) {
        float v0 = (lane < 8) ? s[0][lane] : 0.f;
        float v1 = (lane < 8) ? s[1][lane] : 0.f;
        float v2 = (lane < 8) ? s[2][lane] : 0.f;
        float v3 = (lane < 8) ? s[3][lane] : 0.f;
        float v4 = (lane < 8) ? s[4][lane] : 0.f;
        #pragma unroll
        for (int off = 4; off > 0; off >>= 1) {
            v0 += __shfl_down_sync(0xFFFFFFFFu, v0, off);
            v1 += __shfl_down_sync(0xFFFFFFFFu, v1, off);
            v2 += __shfl_down_sync(0xFFFFFFFFu, v2, off);
            v3 += __shfl_down_sync(0xFFFFFFFFu, v3, off);
            v4 += __shfl_down_sync(0xFFFFFFFFu, v4, off);
        }
        if (lane == 0) {
            atomicAdd(&g_acc[0], (double)v0);
            atomicAdd(&g_acc[1], (double)v1);
            atomicAdd(&g_acc[2], (double)v2);
            atomicAdd(&g_acc[3], (double)v3);
            atomicAdd(&g_acc[4], (double)v4);
        }
    }
}

__global__ void star_finalize_kernel(float* __restrict__ out, double invM)
{
    if (threadIdx.x == 0) {
        double D1  = g_acc[0];
        double D2  = g_acc[1];
        double SW1 = g_acc[2];
        double SW2 = g_acc[3];
        double STR = g_acc[4];
        // omega = 1.0 -> regularizer term is 0.5 * trace
        double r = (SW1 * D1 + SW2 * D2 + 0.5 * STR) * invM;
        out[0] = (float)r;
    }
}

extern "C" void kernel_launch(void* const* d_in, const int* in_sizes, int n_in,
                              void* d_out, int out_size)
{
    const float4* pred2 = (const float4*)d_in[0];  // (B,N,2) f32
    const float4* cov   = (const float4*)d_in[1];  // (B,N,2,2) f32
    const float4* targ2 = (const float4*)d_in[2];  // (B,N,2) f32
    float* out = (float*)d_out;

    long long M = (long long)in_sizes[0] / 2;      // number of 2x2 problems
    int npairs  = (int)(M / 2);                    // two problems per float4 of pred

    star_zero_kernel<<<1, 32>>>();
    star_main_kernel<<<4096, 256>>>(pred2, cov, targ2, npairs);
    star_finalize_kernel<<<1, 32>>>(out, 1.0 / (double)M);
}